// round 11
// baseline (speedup 1.0000x reference)
#include <cuda_runtime.h>
#include <cuda_bf16.h>

#define IMH 4096
#define IMW 4096
#define RAD 8
#define BX 128
#define OUT_W 112
#define CHUNK 16
#define SEGH 256
#define NSTRIPS ((IMW + OUT_W - 1) / OUT_W)   // 37
#define NSEG (IMH / SEGH)                     // 16 -> grid 1776 = 3.0 waves @ 4 CTAs/SM
#define EPSF 1e-4f
#define IRING 24

// ~53 KB -> 4 CTAs/SM. Odd strides (129/113) keep row-indexed access
// conflict-free; float2 vbuf -> LDS.64 (2 wavefronts, 0 conflicts).
struct SmemT {
    float  i_ring[IRING][BX + 1];   // rows y0..y0+23 of i (HF center reads)
    float2 vb_ip [CHUNK][BX + 1];   // (vsum_i, vsum_p)
    float2 vb_pii[CHUNK][BX + 1];   // (vsum_pi, vsum_ii)
    float  qbuf[CHUNK][OUT_W + 1];  // staged outputs for coalesced store
    float  invnx[OUT_W];            // per-column 1/nx (block-constant)
};

__global__ void __launch_bounds__(BX, 4)
gf_kernel(const float* __restrict__ gI, const float* __restrict__ gP,
          float* __restrict__ gQ)
{
    extern __shared__ unsigned char smem_raw[];
    SmemT& sm = *reinterpret_cast<SmemT*>(smem_raw);

    const int tid = threadIdx.x;
    const int ys  = blockIdx.y * SEGH;
    const int chOff = blockIdx.z * IMH * IMW;
    const float* Ic = gI + chOff;
    const float* Pc = gP + chOff;
    float*       Qc = gQ + chOff;

    const int X0 = blockIdx.x * OUT_W;
    const int c  = X0 - RAD + tid;
    const bool cvalid = (c >= 0) && (c < IMW);

    // Per-column 1/nx table (consumed after B1; no extra barrier needed).
    if (tid < OUT_W) {
        const int gx = X0 + tid;
        const int nx = min(gx + RAD, IMW - 1) - max(gx - RAD, 0) + 1;
        sm.invnx[tid] = __fdividef(1.0f, (float)nx);
    }

    float vs_i = 0.f, vs_p = 0.f, vs_pi = 0.f, vs_ii = 0.f;

    // Warmup: accumulate rows ys-9 .. ys+7 (17 rows); stash i rows into ring.
    for (int yl = ys - RAD - 1; yl <= ys + RAD - 1; ++yl) {
        float iv = 0.f, pv = 0.f;
        if (yl >= 0 && cvalid) {
            iv = Ic[yl * IMW + c];
            pv = Pc[yl * IMW + c];
        }
        sm.i_ring[(yl + 2 * IRING) % IRING][tid] = iv;
        vs_i += iv; vs_p += pv; vs_pi += iv * pv; vs_ii += iv * iv;
    }

    int sL  = (ys + RAD) % IRING;   // ring slot for leading row y+8
    int y0m = ys % IRING;           // chunk-base slot for HF reads

    const int hr = tid & 15;        // HF row within chunk
    const int hs = tid >> 4;        // HF x-split (8 splits x 14 cols)
    const int xbase = RAD + 14 * hs;

    for (int ck = 0; ck < SEGH / CHUNK; ++ck) {
        const int y0 = ys + ck * CHUNK;

        // ---- V phase: vertical sliding box sums; trailing edge re-read
        // from gmem (L2-resident). Unroll 8 front-batches LDGs (MLP). ----
        #pragma unroll 8
        for (int r = 0; r < CHUNK; ++r) {
            const int yl = y0 + r + RAD;
            const int yt = y0 + r - RAD - 1;
            float iv = 0.f, pv = 0.f, it = 0.f, pt = 0.f;
            if (yl < IMH && cvalid) {
                iv = __ldg(Ic + yl * IMW + c);
                pv = __ldg(Pc + yl * IMW + c);
            }
            if (yt >= 0 && cvalid) {
                it = __ldg(Ic + yt * IMW + c);
                pt = __ldg(Pc + yt * IMW + c);
            }
            sm.i_ring[sL][tid] = iv;
            vs_i  += iv - it;
            vs_p  += pv - pt;
            vs_pi += iv * pv - it * pt;
            vs_ii += iv * iv - it * it;
            sm.vb_ip [r][tid] = make_float2(vs_i, vs_p);
            sm.vb_pii[r][tid] = make_float2(vs_pi, vs_ii);
            sL = (sL + 1 == IRING) ? 0 : sL + 1;
        }
        __syncthreads();   // B1: vbuf + i_ring (+ invnx) ready

        // ---- HF phase: horizontal sliding sums + guided-filter math ----
        {
            const int y = y0 + hr;
            int sy = y0m + hr; if (sy >= IRING) sy -= IRING;
            // Per-row normalization hoisted: one MUFU per 14 outputs.
            const int ny = min(y + RAD, IMH - 1) - max(y - RAD, 0) + 1;
            const float invNy = __fdividef(1.0f, (float)ny);

            float hi = 0.f, hp = 0.f, hpi = 0.f, hii = 0.f;
            #pragma unroll
            for (int d = -RAD; d <= RAD; ++d) {
                const float2 a2 = sm.vb_ip [hr][xbase + d];
                const float2 b2 = sm.vb_pii[hr][xbase + d];
                hi += a2.x; hp += a2.y; hpi += b2.x; hii += b2.y;
            }
            #pragma unroll
            for (int j = 0; j < 14; ++j) {
                const int x = xbase + j;
                if (j > 0) {
                    const float2 aL = sm.vb_ip [hr][x + RAD];
                    const float2 aT = sm.vb_ip [hr][x - RAD - 1];
                    const float2 bL = sm.vb_pii[hr][x + RAD];
                    const float2 bT = sm.vb_pii[hr][x - RAD - 1];
                    hi  += aL.x - aT.x; hp  += aL.y - aT.y;
                    hpi += bL.x - bT.x; hii += bL.y - bT.y;
                }
                const float invN = invNy * sm.invnx[x - RAD];

                const float m_i  = hi  * invN;
                const float m_p  = hp  * invN;
                const float m_pi = hpi * invN;
                const float m_ii = hii * invN;
                const float cov_ip = m_pi - m_p * m_i;
                const float cov_ii = m_ii - m_i * m_i;
                const float a = __fdividef(cov_ip, cov_ii + EPSF);
                const float b = m_p - a * m_i;
                const float icen = sm.i_ring[sy][x];
                const float q = fminf(fmaxf(a * icen + b, 0.0f), 1.0f);
                sm.qbuf[hr][x - RAD] = q;
            }
        }
        __syncthreads();   // B2: qbuf ready, vbuf free

        // ---- Q phase: coalesced store; overlaps next chunk's V phase ----
        if (tid < OUT_W && (X0 + tid) < IMW) {
            #pragma unroll 4
            for (int rr = 0; rr < CHUNK; ++rr) {
                Qc[(y0 + rr) * IMW + X0 + tid] = sm.qbuf[rr][tid];
            }
        }

        y0m += CHUNK; if (y0m >= IRING) y0m -= IRING;
    }
}

extern "C" void kernel_launch(void* const* d_in, const int* in_sizes, int n_in,
                              void* d_out, int out_size)
{
    const float* I = (const float*)d_in[0];
    const float* P = (const float*)d_in[1];
    float*       Q = (float*)d_out;

    cudaFuncSetAttribute(gf_kernel, cudaFuncAttributeMaxDynamicSharedMemorySize,
                         (int)sizeof(SmemT));

    dim3 grid(NSTRIPS, NSEG, 3);
    gf_kernel<<<grid, BX, sizeof(SmemT)>>>(I, P, Q);
}

// round 12
// speedup vs baseline: 1.2848x; 1.2848x over previous
#include <cuda_runtime.h>
#include <cuda_bf16.h>

#define IMH 4096
#define IMW 4096
#define RAD 8
#define BX 128
#define OUT_W 112
#define CHUNK 16
#define SEGH 256
#define NSTRIPS ((IMW + OUT_W - 1) / OUT_W)   // 37
#define NSEG (IMH / SEGH)                     // 16 -> grid 1776 = 3.0 waves @ 4 CTAs/SM
#define EPSF 1e-4f
#define IRING 24

// ~51.4 KB -> 4 CTAs/SM. Odd strides (129/113) keep row-indexed access
// conflict-free. vbuf is float4: LDS.128 phases of 8 lanes hit banks
// 4*hr..4*hr+3 -> all 32 banks once per phase -> conflict-free, and half
// the LDS/STS instruction count of the float2 SoA layout.
struct SmemT {
    float  i_ring[IRING][BX + 1];   // rows y0..y0+23 of i (HF center reads)
    float4 vbuf  [CHUNK][BX + 1];   // (vsum_i, vsum_p, vsum_pi, vsum_ii)
    float  qbuf[CHUNK][OUT_W + 1];  // staged outputs for coalesced store
};

__global__ void __launch_bounds__(BX, 4)
gf_kernel(const float* __restrict__ gI, const float* __restrict__ gP,
          float* __restrict__ gQ)
{
    extern __shared__ unsigned char smem_raw[];
    SmemT& sm = *reinterpret_cast<SmemT*>(smem_raw);

    const int tid = threadIdx.x;
    const int ys  = blockIdx.y * SEGH;
    const int chOff = blockIdx.z * IMH * IMW;
    const float* Ic = gI + chOff;
    const float* Pc = gP + chOff;
    float*       Qc = gQ + chOff;

    const int X0 = blockIdx.x * OUT_W;
    const int c  = X0 - RAD + tid;
    const bool cvalid = (c >= 0) && (c < IMW);

    float vs_i = 0.f, vs_p = 0.f, vs_pi = 0.f, vs_ii = 0.f;

    // Warmup: accumulate rows ys-9 .. ys+7 (17 rows); stash i rows into ring.
    for (int yl = ys - RAD - 1; yl <= ys + RAD - 1; ++yl) {
        float iv = 0.f, pv = 0.f;
        if (yl >= 0 && cvalid) {
            iv = Ic[yl * IMW + c];
            pv = Pc[yl * IMW + c];
        }
        sm.i_ring[(yl + 2 * IRING) % IRING][tid] = iv;
        vs_i += iv; vs_p += pv; vs_pi += iv * pv; vs_ii += iv * iv;
    }

    int sL  = (ys + RAD) % IRING;   // ring slot for leading row y+8
    int y0m = ys % IRING;           // chunk-base slot for HF reads

    const int hr = tid & 15;        // HF row within chunk
    const int hs = tid >> 4;        // HF x-split (8 splits x 14 cols)
    const int xbase = RAD + 14 * hs;

    for (int ck = 0; ck < SEGH / CHUNK; ++ck) {
        const int y0 = ys + ck * CHUNK;

        // ---- V phase: vertical sliding box sums; trailing edge re-read
        // from gmem (L2-resident). Unroll 8 front-batches LDGs (MLP). ----
        #pragma unroll 8
        for (int r = 0; r < CHUNK; ++r) {
            const int yl = y0 + r + RAD;
            const int yt = y0 + r - RAD - 1;
            float iv = 0.f, pv = 0.f, it = 0.f, pt = 0.f;
            if (yl < IMH && cvalid) {
                iv = __ldg(Ic + yl * IMW + c);
                pv = __ldg(Pc + yl * IMW + c);
            }
            if (yt >= 0 && cvalid) {
                it = __ldg(Ic + yt * IMW + c);
                pt = __ldg(Pc + yt * IMW + c);
            }
            sm.i_ring[sL][tid] = iv;
            vs_i  += iv - it;
            vs_p  += pv - pt;
            vs_pi += iv * pv - it * pt;
            vs_ii += iv * iv - it * it;
            sm.vbuf[r][tid] = make_float4(vs_i, vs_p, vs_pi, vs_ii);
            sL = (sL + 1 == IRING) ? 0 : sL + 1;
        }
        __syncthreads();   // B1: vbuf + i_ring ready

        // ---- HF phase: horizontal sliding sums + guided-filter math ----
        {
            const int y = y0 + hr;
            int sy = y0m + hr; if (sy >= IRING) sy -= IRING;
            const int ny = min(y + RAD, IMH - 1) - max(y - RAD, 0) + 1;

            float hi = 0.f, hp = 0.f, hpi = 0.f, hii = 0.f;
            #pragma unroll
            for (int d = -RAD; d <= RAD; ++d) {
                const float4 v = sm.vbuf[hr][xbase + d];
                hi += v.x; hp += v.y; hpi += v.z; hii += v.w;
            }
            #pragma unroll
            for (int j = 0; j < 14; ++j) {
                const int x = xbase + j;
                if (j > 0) {
                    const float4 vL = sm.vbuf[hr][x + RAD];
                    const float4 vT = sm.vbuf[hr][x - RAD - 1];
                    hi  += vL.x - vT.x; hp  += vL.y - vT.y;
                    hpi += vL.z - vT.z; hii += vL.w - vT.w;
                }
                const int gx = X0 + x - RAD;
                const int nx = min(gx + RAD, IMW - 1) - max(gx - RAD, 0) + 1;
                const float invN = __fdividef(1.0f, (float)(ny * nx));

                const float m_i  = hi  * invN;
                const float m_p  = hp  * invN;
                const float m_pi = hpi * invN;
                const float m_ii = hii * invN;
                const float cov_ip = m_pi - m_p * m_i;
                const float cov_ii = m_ii - m_i * m_i;
                const float a = __fdividef(cov_ip, cov_ii + EPSF);
                const float b = m_p - a * m_i;
                const float icen = sm.i_ring[sy][x];
                const float q = fminf(fmaxf(a * icen + b, 0.0f), 1.0f);
                sm.qbuf[hr][x - RAD] = q;
            }
        }
        __syncthreads();   // B2: qbuf ready, vbuf free

        // ---- Q phase: coalesced store; overlaps next chunk's V phase ----
        if (tid < OUT_W && (X0 + tid) < IMW) {
            #pragma unroll 4
            for (int rr = 0; rr < CHUNK; ++rr) {
                Qc[(y0 + rr) * IMW + X0 + tid] = sm.qbuf[rr][tid];
            }
        }

        y0m += CHUNK; if (y0m >= IRING) y0m -= IRING;
    }
}

extern "C" void kernel_launch(void* const* d_in, const int* in_sizes, int n_in,
                              void* d_out, int out_size)
{
    const float* I = (const float*)d_in[0];
    const float* P = (const float*)d_in[1];
    float*       Q = (float*)d_out;

    cudaFuncSetAttribute(gf_kernel, cudaFuncAttributeMaxDynamicSharedMemorySize,
                         (int)sizeof(SmemT));

    dim3 grid(NSTRIPS, NSEG, 3);
    gf_kernel<<<grid, BX, sizeof(SmemT)>>>(I, P, Q);
}

// round 13
// speedup vs baseline: 1.3655x; 1.0628x over previous
#include <cuda_runtime.h>
#include <cuda_fp16.h>

#define IMH 4096
#define IMW 4096
#define RAD 8
#define BX 128
#define OUT_W 112
#define CHUNK 16
#define SEGH 256
#define NSTRIPS ((IMW + OUT_W - 1) / OUT_W)   // 37
#define NSEG (IMH / SEGH)                     // 16 -> grid 1776
#define EPSF 1e-4f

// 44.9 KB -> 5 CTAs/SM (224.6/228 KB). Odd strides (129/113) keep
// row-indexed access conflict-free; float2 vbuf -> LDS.64, no conflicts.
struct SmemT {
    float2 vb_ip [CHUNK][BX + 1];   // (vsum_i, vsum_p)
    float2 vb_pii[CHUNK][BX + 1];   // (vsum_pi, vsum_ii)
    float  icen  [CHUNK][BX + 1];   // center-row i (from reg delay line)
    __half qbuf  [CHUNK][OUT_W + 1];// staged outputs (half: rel err <= 4.9e-4)
};

__global__ void __launch_bounds__(BX, 5)
gf_kernel(const float* __restrict__ gI, const float* __restrict__ gP,
          float* __restrict__ gQ)
{
    extern __shared__ unsigned char smem_raw[];
    SmemT& sm = *reinterpret_cast<SmemT*>(smem_raw);

    const int tid = threadIdx.x;
    const int ys  = blockIdx.y * SEGH;
    const int chOff = blockIdx.z * IMH * IMW;
    const float* Ic = gI + chOff;
    const float* Pc = gP + chOff;
    float*       Qc = gQ + chOff;

    const int X0 = blockIdx.x * OUT_W;
    const int c  = X0 - RAD + tid;
    const bool cvalid = (c >= 0) && (c < IMW);

    float vs_i = 0.f, vs_p = 0.f, vs_pi = 0.f, vs_ii = 0.f;
    float dly[8];                       // i delay line: dly[0] = oldest
    #pragma unroll
    for (int k = 0; k < 8; ++k) dly[k] = 0.f;

    // Warmup: accumulate rows ys-9 .. ys+7 (17 rows). The last 8 iterations
    // (rows ys..ys+7) leave the delay line holding exactly those i values.
    #pragma unroll
    for (int w = 0; w < 17; ++w) {
        const int yl = ys - RAD - 1 + w;
        float iv = 0.f, pv = 0.f;
        if (yl >= 0 && cvalid) {
            iv = Ic[yl * IMW + c];
            pv = Pc[yl * IMW + c];
        }
        vs_i += iv; vs_p += pv; vs_pi += iv * pv; vs_ii += iv * iv;
        #pragma unroll
        for (int k = 0; k < 7; ++k) dly[k] = dly[k + 1];
        dly[7] = iv;
    }

    const int hr = tid & 15;        // HF row within chunk
    const int hs = tid >> 4;        // HF x-split (8 splits x 14 cols)
    const int xbase = RAD + 14 * hs;

    for (int ck = 0; ck < SEGH / CHUNK; ++ck) {
        const int y0 = ys + ck * CHUNK;

        // ---- V phase: vertical sliding box sums; trailing edge re-read
        // from gmem (L2-resident). Unroll 8 front-batches LDGs (MLP).
        // dly[0] == i(row y0+r): written to icen for HF center reads. ----
        #pragma unroll 8
        for (int r = 0; r < CHUNK; ++r) {
            const int yl = y0 + r + RAD;
            const int yt = y0 + r - RAD - 1;
            float iv = 0.f, pv = 0.f, it = 0.f, pt = 0.f;
            if (yl < IMH && cvalid) {
                iv = __ldg(Ic + yl * IMW + c);
                pv = __ldg(Pc + yl * IMW + c);
            }
            if (yt >= 0 && cvalid) {
                it = __ldg(Ic + yt * IMW + c);
                pt = __ldg(Pc + yt * IMW + c);
            }
            sm.icen[r][tid] = dly[0];
            #pragma unroll
            for (int k = 0; k < 7; ++k) dly[k] = dly[k + 1];
            dly[7] = iv;
            vs_i  += iv - it;
            vs_p  += pv - pt;
            vs_pi += iv * pv - it * pt;
            vs_ii += iv * iv - it * it;
            sm.vb_ip [r][tid] = make_float2(vs_i, vs_p);
            sm.vb_pii[r][tid] = make_float2(vs_pi, vs_ii);
        }
        __syncthreads();   // B1: vbuf + icen ready

        // ---- HF phase: horizontal sliding sums + guided-filter math ----
        {
            const int y = y0 + hr;
            const int ny = min(y + RAD, IMH - 1) - max(y - RAD, 0) + 1;

            float hi = 0.f, hp = 0.f, hpi = 0.f, hii = 0.f;
            #pragma unroll
            for (int d = -RAD; d <= RAD; ++d) {
                const float2 a2 = sm.vb_ip [hr][xbase + d];
                const float2 b2 = sm.vb_pii[hr][xbase + d];
                hi += a2.x; hp += a2.y; hpi += b2.x; hii += b2.y;
            }
            #pragma unroll
            for (int j = 0; j < 14; ++j) {
                const int x = xbase + j;
                if (j > 0) {
                    const float2 aL = sm.vb_ip [hr][x + RAD];
                    const float2 aT = sm.vb_ip [hr][x - RAD - 1];
                    const float2 bL = sm.vb_pii[hr][x + RAD];
                    const float2 bT = sm.vb_pii[hr][x - RAD - 1];
                    hi  += aL.x - aT.x; hp  += aL.y - aT.y;
                    hpi += bL.x - bT.x; hii += bL.y - bT.y;
                }
                const int gx = X0 + x - RAD;
                const int nx = min(gx + RAD, IMW - 1) - max(gx - RAD, 0) + 1;
                const float invN = __fdividef(1.0f, (float)(ny * nx));

                const float m_i  = hi  * invN;
                const float m_p  = hp  * invN;
                const float m_pi = hpi * invN;
                const float m_ii = hii * invN;
                const float cov_ip = m_pi - m_p * m_i;
                const float cov_ii = m_ii - m_i * m_i;
                const float a = __fdividef(cov_ip, cov_ii + EPSF);
                const float b = m_p - a * m_i;
                const float icen = sm.icen[hr][x];
                const float q = fminf(fmaxf(a * icen + b, 0.0f), 1.0f);
                sm.qbuf[hr][x - RAD] = __float2half_rn(q);
            }
        }
        __syncthreads();   // B2: qbuf ready, vbuf free

        // ---- Q phase: coalesced store; overlaps next chunk's V phase ----
        if (tid < OUT_W && (X0 + tid) < IMW) {
            #pragma unroll 4
            for (int rr = 0; rr < CHUNK; ++rr) {
                Qc[(y0 + rr) * IMW + X0 + tid] = __half2float(sm.qbuf[rr][tid]);
            }
        }
    }
}

extern "C" void kernel_launch(void* const* d_in, const int* in_sizes, int n_in,
                              void* d_out, int out_size)
{
    const float* I = (const float*)d_in[0];
    const float* P = (const float*)d_in[1];
    float*       Q = (float*)d_out;

    cudaFuncSetAttribute(gf_kernel, cudaFuncAttributeMaxDynamicSharedMemorySize,
                         (int)sizeof(SmemT));

    dim3 grid(NSTRIPS, NSEG, 3);
    gf_kernel<<<grid, BX, sizeof(SmemT)>>>(I, P, Q);
}